// round 8
// baseline (speedup 1.0000x reference)
#include <cuda_runtime.h>
#include <cuda_bf16.h>
#include <cstdint>

#define D_MODEL   1024
#define NUM_HEADS 16
#define D_HEAD    64
#define BATCH     4
#define SEQ       2048
#define MTOT      (BATCH * SEQ)   // 8192
#define QKV_EL    (BATCH * NUM_HEADS * SEQ * D_HEAD)   // 8388608

// ---------------- scratch (device globals: allocation-guard safe) ----------
__device__ __nv_bfloat16 g_xh[MTOT * D_MODEL],  g_xl[MTOT * D_MODEL];
__device__ __nv_bfloat16 g_wh[4][D_MODEL * D_MODEL], g_wl[4][D_MODEL * D_MODEL];
__device__ __nv_bfloat16 g_qh[QKV_EL], g_ql[QKV_EL];          // [b,h,s,d]
__device__ __nv_bfloat16 g_kh[QKV_EL], g_kl[QKV_EL];          // [b,h,s,d]
__device__ __nv_bfloat16 g_vth[QKV_EL], g_vtl[QKV_EL];        // [b,h,d,s]
__device__ __nv_bfloat16 g_ch[MTOT * D_MODEL], g_cl[MTOT * D_MODEL];   // ctx

// ---------------- helpers ----------------------------------------------------
__device__ __forceinline__ void split_bf(float x, __nv_bfloat16& h, __nv_bfloat16& l) {
    h = __float2bfloat16(x);
    l = __float2bfloat16(x - __bfloat162float(h));
}
__device__ __forceinline__ unsigned pk(__nv_bfloat16 a, __nv_bfloat16 b) {
    return (unsigned)__bfloat16_as_ushort(a) | ((unsigned)__bfloat16_as_ushort(b) << 16);
}
__device__ __forceinline__ void split_store4(float4 v, __nv_bfloat16* hp, __nv_bfloat16* lp) {
    __nv_bfloat16 h0, l0, h1, l1, h2, l2, h3, l3;
    split_bf(v.x, h0, l0); split_bf(v.y, h1, l1);
    split_bf(v.z, h2, l2); split_bf(v.w, h3, l3);
    *(uint2*)hp = make_uint2(pk(h0, h1), pk(h2, h3));
    *(uint2*)lp = make_uint2(pk(l0, l1), pk(l2, l3));
}
__device__ __forceinline__ void mma16(float* c, const unsigned* a, unsigned b0, unsigned b1) {
    asm volatile(
        "mma.sync.aligned.m16n8k16.row.col.f32.bf16.bf16.f32 "
        "{%0,%1,%2,%3}, {%4,%5,%6,%7}, {%8,%9}, {%0,%1,%2,%3};"
        : "+f"(c[0]), "+f"(c[1]), "+f"(c[2]), "+f"(c[3])
        : "r"(a[0]), "r"(a[1]), "r"(a[2]), "r"(a[3]), "r"(b0), "r"(b1));
}
__device__ __forceinline__ void ldsm4(unsigned r[4], const __nv_bfloat16* p) {
    unsigned a = (unsigned)__cvta_generic_to_shared(p);
    asm volatile("ldmatrix.sync.aligned.m8n8.x4.shared.b16 {%0,%1,%2,%3}, [%4];"
                 : "=r"(r[0]), "=r"(r[1]), "=r"(r[2]), "=r"(r[3]) : "r"(a));
}
__device__ __forceinline__ void cp16(__nv_bfloat16* s, const __nv_bfloat16* g) {
    unsigned sa = (unsigned)__cvta_generic_to_shared(s);
    asm volatile("cp.async.cg.shared.global [%0], [%1], 16;" :: "r"(sa), "l"(g));
}
#define CP_COMMIT() asm volatile("cp.async.commit_group;")
#define CP_WAIT0()  asm volatile("cp.async.wait_group 0;")
#define CP_WAIT1()  asm volatile("cp.async.wait_group 1;")

// fast exp2 on the FMA pipe (MUFU-free)
__device__ __forceinline__ float exp2_fast(float y) {
    y = fmaxf(y, -120.f);
    float z = y + 12582912.f;
    int   e = __float_as_int(z);
    float f = y - (z - 12582912.f);
    float p = 1.f + f * (0.6931471805599453f + f * (0.2402265069591007f +
              f * (0.0555041086648216f + f * (0.0096181291076285f +
              f * 0.0013333558146429f))));
    return __int_as_float(__float_as_int(p) + (e << 23));
}
#define SCALE_LOG2E 0.18033688011112042f   // 0.125 * log2(e)

// ---------------- one-shot split of x + weights ------------------------------
__global__ __launch_bounds__(256) void split_all(const float* __restrict__ x,
                                                 const float* __restrict__ Qw,
                                                 const float* __restrict__ Kw,
                                                 const float* __restrict__ Vw,
                                                 const float* __restrict__ Ow)
{
    const int idx = blockIdx.x * 256 + threadIdx.x;        // one float4 each
    const float* src;
    __nv_bfloat16 *hp, *lp;
    size_t off;
    if (idx < 2097152) {
        src = x; off = idx; hp = g_xh; lp = g_xl;
    } else {
        const int w = (idx - 2097152) >> 18;
        off = (size_t)((idx - 2097152) & 262143);
        src = (w == 0) ? Qw : (w == 1) ? Kw : (w == 2) ? Vw : Ow;
        hp = g_wh[w]; lp = g_wl[w];
    }
    float4 v = ((const float4*)src)[off];
    split_store4(v, hp + off * 4, lp + off * 4);
}

// ---------------- split-bf16 GEMM, cp.async + ldmatrix -----------------------
// Block tile 128x128, BK=32, 256 threads = 8 warps (4m x 2n), warp tile 32x64.
// mma issue order is TERM-MAJOR across 8 accumulators -> dependent spacing 8.
#define SSTR 40
#define GBUF (128 * SSTR)
#define GSTG (4 * GBUF)
#define GEMM_SMEM (2 * GSTG * 2)      // 81920 bytes

__device__ __forceinline__ void gemm_bf_body(const __nv_bfloat16* __restrict__ Agh,
                                             const __nv_bfloat16* __restrict__ Agl,
                                             const __nv_bfloat16* __restrict__ Bgh,
                                             const __nv_bfloat16* __restrict__ Bgl,
                                             int m0, int n0,
                                             float (&c)[2][8][4],
                                             __nv_bfloat16* sm)
{
    const int tid  = threadIdx.x;
    const int lane = tid & 31;
    const int warp = tid >> 5;
    const int wm   = (warp >> 1) * 32;
    const int wn   = (warp & 1) * 64;
    const int lrow = tid >> 1;
    const int lcol = (tid & 1) * 16;
    const int so   = lrow * SSTR + lcol;

    const int aoff = ((lane & 7) + ((lane >> 3) & 1) * 8) * SSTR + (lane >> 4) * 8;
    const int boff = ((lane & 7) + (lane >> 4) * 8) * SSTR + ((lane >> 3) & 1) * 8;

    const size_t arow = (size_t)(m0 + lrow) * D_MODEL + lcol;
    const size_t brow = (size_t)(n0 + lrow) * D_MODEL + lcol;

    {   // prologue: stage 0 <- k-tile 0
        __nv_bfloat16* st = sm;
        cp16(st + so,            Agh + arow); cp16(st + so + 8,            Agh + arow + 8);
        cp16(st + GBUF + so,     Agl + arow); cp16(st + GBUF + so + 8,     Agl + arow + 8);
        cp16(st + 2 * GBUF + so, Bgh + brow); cp16(st + 2 * GBUF + so + 8, Bgh + brow + 8);
        cp16(st + 3 * GBUF + so, Bgl + brow); cp16(st + 3 * GBUF + so + 8, Bgl + brow + 8);
        CP_COMMIT();
        CP_WAIT0();
    }
    __syncthreads();

    for (int kt = 0; kt < 32; kt++) {
        if (kt + 1 < 32) {
            __nv_bfloat16* nx = sm + ((kt + 1) & 1) * GSTG;
            const int k0 = (kt + 1) * 32;
            cp16(nx + so,            Agh + arow + k0); cp16(nx + so + 8,            Agh + arow + k0 + 8);
            cp16(nx + GBUF + so,     Agl + arow + k0); cp16(nx + GBUF + so + 8,     Agl + arow + k0 + 8);
            cp16(nx + 2 * GBUF + so, Bgh + brow + k0); cp16(nx + 2 * GBUF + so + 8, Bgh + brow + k0 + 8);
            cp16(nx + 3 * GBUF + so, Bgl + brow + k0); cp16(nx + 3 * GBUF + so + 8, Bgl + brow + k0 + 8);
            CP_COMMIT();
        }

        const __nv_bfloat16* Ah = sm + (kt & 1) * GSTG;
        const __nv_bfloat16* Al = Ah + GBUF;
        const __nv_bfloat16* Bh = Ah + 2 * GBUF;
        const __nv_bfloat16* Bl = Ah + 3 * GBUF;

        #pragma unroll
        for (int ks = 0; ks < 2; ks++) {
            const int kk = ks * 16;
            unsigned ahi[2][4], alo[2][4];
            ldsm4(ahi[0], Ah + (wm     ) * SSTR + kk + aoff);
            ldsm4(ahi[1], Ah + (wm + 16) * SSTR + kk + aoff);
            ldsm4(alo[0], Al + (wm     ) * SSTR + kk + aoff);
            ldsm4(alo[1], Al + (wm + 16) * SSTR + kk + aoff);
            #pragma unroll
            for (int p = 0; p < 2; p++) {
                unsigned bh0[4], bl0[4], bh1[4], bl1[4];
                ldsm4(bh0, Bh + (wn + 32 * p     ) * SSTR + kk + boff);
                ldsm4(bl0, Bl + (wn + 32 * p     ) * SSTR + kk + boff);
                ldsm4(bh1, Bh + (wn + 32 * p + 16) * SSTR + kk + boff);
                ldsm4(bl1, Bl + (wn + 32 * p + 16) * SSTR + kk + boff);
                const int j0 = 4 * p;
                // term hi*hi  (8 independent accumulators)
                mma16(c[0][j0 + 0], ahi[0], bh0[0], bh0[1]);
                mma16(c[1][j0 + 0], ahi[1], bh0[0], bh0[1]);
                mma16(c[0][j0 + 1], ahi[0], bh0[2], bh0[3]);
                mma16(c[1][j0 + 1], ahi[1], bh0[2], bh0[3]);
                mma16(c[0][j0 + 2], ahi[0], bh1[0], bh1[1]);
                mma16(c[1][j0 + 2], ahi[1], bh1[0], bh1[1]);
                mma16(c[0][j0 + 3], ahi[0], bh1[2], bh1[3]);
                mma16(c[1][j0 + 3], ahi[1], bh1[2], bh1[3]);
                // term lo*hi
                mma16(c[0][j0 + 0], alo[0], bh0[0], bh0[1]);
                mma16(c[1][j0 + 0], alo[1], bh0[0], bh0[1]);
                mma16(c[0][j0 + 1], alo[0], bh0[2], bh0[3]);
                mma16(c[1][j0 + 1], alo[1], bh0[2], bh0[3]);
                mma16(c[0][j0 + 2], alo[0], bh1[0], bh1[1]);
                mma16(c[1][j0 + 2], alo[1], bh1[0], bh1[1]);
                mma16(c[0][j0 + 3], alo[0], bh1[2], bh1[3]);
                mma16(c[1][j0 + 3], alo[1], bh1[2], bh1[3]);
                // term hi*lo
                mma16(c[0][j0 + 0], ahi[0], bl0[0], bl0[1]);
                mma16(c[1][j0 + 0], ahi[1], bl0[0], bl0[1]);
                mma16(c[0][j0 + 1], ahi[0], bl0[2], bl0[3]);
                mma16(c[1][j0 + 1], ahi[1], bl0[2], bl0[3]);
                mma16(c[0][j0 + 2], ahi[0], bl1[0], bl1[1]);
                mma16(c[1][j0 + 2], ahi[1], bl1[0], bl1[1]);
                mma16(c[0][j0 + 3], ahi[0], bl1[2], bl1[3]);
                mma16(c[1][j0 + 3], ahi[1], bl1[2], bl1[3]);
            }
        }
        CP_WAIT0();
        __syncthreads();
    }
}

// Fused QKV projection; blockIdx.z selects weight.
__global__ __launch_bounds__(256, 2) void gemm_qkv()
{
    extern __shared__ __nv_bfloat16 smg[];
    float c[2][8][4];
    #pragma unroll
    for (int i = 0; i < 2; i++)
        #pragma unroll
        for (int j = 0; j < 8; j++)
            #pragma unroll
            for (int q = 0; q < 4; q++) c[i][j][q] = 0.f;

    const int m0 = blockIdx.y * 128;
    const int n0 = blockIdx.x * 128;
    const int z  = blockIdx.z;

    gemm_bf_body(g_xh, g_xl, g_wh[z], g_wl[z], m0, n0, c, smg);

    const int lane = threadIdx.x & 31;
    const int g = lane >> 2, t = lane & 3;
    const int warp = threadIdx.x >> 5;
    const int wm = (warp >> 1) * 32, wn = (warp & 1) * 64;

    #pragma unroll
    for (int i = 0; i < 2; i++) {
        #pragma unroll
        for (int j = 0; j < 8; j++) {
            const int n = n0 + wn + 8 * j + 2 * t;
            const int h = n >> 6, d = n & 63;
            const int r0 = m0 + wm + 16 * i + g;
            const int r1 = r0 + 8;
            const int b0 = r0 >> 11, s0 = r0 & 2047;
            const int b1 = r1 >> 11, s1 = r1 & 2047;
            __nv_bfloat16 h0, l0, h1, l1, h2, l2, h3, l3;
            split_bf(c[i][j][0], h0, l0); split_bf(c[i][j][1], h1, l1);
            split_bf(c[i][j][2], h2, l2); split_bf(c[i][j][3], h3, l3);
            if (z == 2) {
                const size_t v0 = ((size_t)(b0 * NUM_HEADS + h) * D_HEAD + d) * SEQ + s0;
                const size_t v1 = ((size_t)(b1 * NUM_HEADS + h) * D_HEAD + d) * SEQ + s1;
                g_vth[v0] = h0; g_vtl[v0] = l0;
                g_vth[v0 + SEQ] = h1; g_vtl[v0 + SEQ] = l1;
                g_vth[v1] = h2; g_vtl[v1] = l2;
                g_vth[v1 + SEQ] = h3; g_vtl[v1 + SEQ] = l3;
            } else {
                __nv_bfloat16* dh = (z == 0) ? g_qh : g_kh;
                __nv_bfloat16* dl = (z == 0) ? g_ql : g_kl;
                const size_t i0 = ((size_t)(b0 * NUM_HEADS + h) * SEQ + s0) * D_HEAD + d;
                const size_t i1 = ((size_t)(b1 * NUM_HEADS + h) * SEQ + s1) * D_HEAD + d;
                *(unsigned*)&dh[i0] = pk(h0, h1);
                *(unsigned*)&dl[i0] = pk(l0, l1);
                *(unsigned*)&dh[i1] = pk(h2, h3);
                *(unsigned*)&dl[i1] = pk(l2, l3);
            }
        }
    }
}

// Output projection: out = ctx @ Ow^T, fp32 out.
__global__ __launch_bounds__(256, 2) void gemm_out(float* __restrict__ out)
{
    extern __shared__ __nv_bfloat16 smg[];
    float c[2][8][4];
    #pragma unroll
    for (int i = 0; i < 2; i++)
        #pragma unroll
        for (int j = 0; j < 8; j++)
            #pragma unroll
            for (int q = 0; q < 4; q++) c[i][j][q] = 0.f;

    const int m0 = blockIdx.y * 128;
    const int n0 = blockIdx.x * 128;

    gemm_bf_body(g_ch, g_cl, g_wh[3], g_wl[3], m0, n0, c, smg);

    const int lane = threadIdx.x & 31;
    const int g = lane >> 2, t = lane & 3;
    const int warp = threadIdx.x >> 5;
    const int wm = (warp >> 1) * 32, wn = (warp & 1) * 64;

    #pragma unroll
    for (int i = 0; i < 2; i++) {
        #pragma unroll
        for (int j = 0; j < 8; j++) {
            const int n  = n0 + wn + 8 * j + 2 * t;
            const int r0 = m0 + wm + 16 * i + g;
            *(float2*)&out[(size_t)r0 * D_MODEL + n] = make_float2(c[i][j][0], c[i][j][1]);
            *(float2*)&out[(size_t)(r0 + 8) * D_MODEL + n] = make_float2(c[i][j][2], c[i][j][3]);
        }
    }
}

// ---------------- Flash attention: Q-in-regs, KV double-buffer, ldmatrix -----
// Term-major mma ordering across 4-accumulator groups (spacing 4).
#define QSTR 72
#define TILEC (64 * QSTR)
#define ATTN_SMEM (12 * TILEC * 2)        // 110592 bytes

__global__ __launch_bounds__(256, 2) void attn_mma(const unsigned char* __restrict__ pm)
{
    extern __shared__ __nv_bfloat16 smb[];
    __nv_bfloat16* stg0 = smb;
    __nv_bfloat16* stg1 = smb + 4 * TILEC;
    __nv_bfloat16* Ph   = smb + 8 * TILEC;
    __nv_bfloat16* Pl   = smb + 10 * TILEC;

    const int qt = gridDim.x - 1 - blockIdx.x;
    const int h  = blockIdx.y;
    const int b  = blockIdx.z;
    const int tid  = threadIdx.x;
    const int lane = tid & 31;
    const int warp = tid >> 5;
    const int g = lane >> 2, t = lane & 3;
    const size_t base = (size_t)(b * NUM_HEADS + h) * SEQ;

    const int rw = warp * 16;
    const int Rg = qt * 128 + rw;
    const int kt_max = 2 * qt + 1;

    const int aoffQ = ((lane & 7) + ((lane >> 3) & 1) * 8) * QSTR + (lane >> 4) * 8;
    const int boffQ = ((lane & 7) + (lane >> 4) * 8) * QSTR + ((lane >> 3) & 1) * 8;

    const int krow = tid >> 2;
    const int kcs  = (tid & 3) * 16;
    const int kso  = krow * QSTR + kcs;
    const size_t vbase = ((size_t)(b * NUM_HEADS + h) * D_HEAD + krow) * SEQ + kcs;
    const size_t kbase = (base + krow) * D_HEAD + kcs;

    {
        const int row = tid >> 1, cs = (tid & 1) * 32;
        const size_t ga = (base + (size_t)qt * 128 + row) * D_HEAD + cs;
        const int so = row * QSTR + cs;
        __nv_bfloat16* Qsh = stg1;
        __nv_bfloat16* Qsl = stg1 + 2 * TILEC;
        #pragma unroll
        for (int u = 0; u < 4; u++) {
            cp16(&Qsh[so + 8 * u], &g_qh[ga + 8 * u]);
            cp16(&Qsl[so + 8 * u], &g_ql[ga + 8 * u]);
        }
        CP_COMMIT();
    }
    {
        cp16(&stg0[kso],             &g_kh[kbase]); cp16(&stg0[kso + 8],             &g_kh[kbase + 8]);
        cp16(&stg0[TILEC + kso],     &g_kl[kbase]); cp16(&stg0[TILEC + kso + 8],     &g_kl[kbase + 8]);
        cp16(&stg0[2 * TILEC + kso], &g_vth[vbase]); cp16(&stg0[2 * TILEC + kso + 8], &g_vth[vbase + 8]);
        cp16(&stg0[3 * TILEC + kso], &g_vtl[vbase]); cp16(&stg0[3 * TILEC + kso + 8], &g_vtl[vbase + 8]);
        CP_COMMIT();
    }
    CP_WAIT1();
    __syncthreads();

    unsigned qh[4][4], ql[4][4];
    #pragma unroll
    for (int ks = 0; ks < 4; ks++) {
        ldsm4(qh[ks], stg1 + rw * QSTR + 16 * ks + aoffQ);
        ldsm4(ql[ks], stg1 + 2 * TILEC + rw * QSTR + 16 * ks + aoffQ);
    }
    __syncthreads();

    float o[8][4];
    float m_i[2] = {-1e30f, -1e30f};
    float l_i[2] = {0.f, 0.f};
    #pragma unroll
    for (int j = 0; j < 8; j++)
        #pragma unroll
        for (int q = 0; q < 4; q++) o[j][q] = 0.f;

    for (int kt = 0; kt <= kt_max; kt++) {
        if (kt < kt_max) {
            __nv_bfloat16* nx = ((kt + 1) & 1) ? stg1 : stg0;
            const size_t gk = kbase + (size_t)(kt + 1) * 64 * D_HEAD;
            const size_t gv = vbase + (size_t)(kt + 1) * 64;
            cp16(&nx[kso],             &g_kh[gk]);  cp16(&nx[kso + 8],             &g_kh[gk + 8]);
            cp16(&nx[TILEC + kso],     &g_kl[gk]);  cp16(&nx[TILEC + kso + 8],     &g_kl[gk + 8]);
            cp16(&nx[2 * TILEC + kso], &g_vth[gv]); cp16(&nx[2 * TILEC + kso + 8], &g_vth[gv + 8]);
            cp16(&nx[3 * TILEC + kso], &g_vtl[gv]); cp16(&nx[3 * TILEC + kso + 8], &g_vtl[gv + 8]);
            CP_COMMIT();
            CP_WAIT1();
        } else {
            CP_WAIT0();
        }
        __syncthreads();

        const int C0 = kt * 64;
        if (C0 <= Rg + 15) {
            const __nv_bfloat16* Kh = (kt & 1) ? stg1 : stg0;
            const __nv_bfloat16* Kl = Kh + TILEC;
            const __nv_bfloat16* Vh = Kh + 2 * TILEC;
            const __nv_bfloat16* Vl = Kh + 3 * TILEC;

            float s[8][4];
            #pragma unroll
            for (int j = 0; j < 8; j++)
                #pragma unroll
                for (int q = 0; q < 4; q++) s[j][q] = 0.f;

            // ---- S = Q @ K^T: pair-blocked, term-major ----
            #pragma unroll
            for (int ks = 0; ks < 4; ks++) {
                const int kk = 16 * ks;
                #pragma unroll
                for (int p = 0; p < 2; p++) {
                    unsigned bh0[4], bl0[4], bh1[4], bl1[4];
                    ldsm4(bh0, Kh + (32 * p     ) * QSTR + kk + boffQ);
                    ldsm4(bl0, Kl + (32 * p     ) * QSTR + kk + boffQ);
                    ldsm4(bh1, Kh + (32 * p + 16) * QSTR + kk + boffQ);
                    ldsm4(bl1, Kl + (32 * p + 16) * QSTR + kk + boffQ);
                    const int j0 = 4 * p;
                    mma16(s[j0 + 0], qh[ks], bh0[0], bh0[1]);
                    mma16(s[j0 + 1], qh[ks], bh0[2], bh0[3]);
                    mma16(s[j0 + 2], qh[ks], bh1[0], bh1[1]);
                    mma16(s[j0 + 3], qh[ks], bh1[2], bh1[3]);
                    mma16(s[j0 + 0], ql[ks], bh0[0], bh0[1]);
                    mma16(s[j0 + 1], ql[ks], bh0[2], bh0[3]);
                    mma16(s[j0 + 2], ql[ks], bh1[0], bh1[1]);
                    mma16(s[j0 + 3], ql[ks], bh1[2], bh1[3]);
                    mma16(s[j0 + 0], qh[ks], bl0[0], bl0[1]);
                    mma16(s[j0 + 1], qh[ks], bl0[2], bl0[3]);
                    mma16(s[j0 + 2], qh[ks], bl1[0], bl1[1]);
                    mma16(s[j0 + 3], qh[ks], bl1[2], bl1[3]);
                }
            }

            const unsigned char* pmb = pm + (size_t)b * SEQ + C0;
            const int r0 = Rg + g, r1 = r0 + 8;
            #pragma unroll
            for (int j = 0; j < 8; j++) {
                const int c0 = C0 + 8 * j + 2 * t, c1 = c0 + 1;
                const bool p0 = pmb[8 * j + 2 * t] != 0;
                const bool p1 = pmb[8 * j + 2 * t + 1] != 0;
                float v;
                v = s[j][0] * SCALE_LOG2E; if (c0 > r0 || p0) v = -1e30f; s[j][0] = v;
                v = s[j][1] * SCALE_LOG2E; if (c1 > r0 || p1) v = -1e30f; s[j][1] = v;
                v = s[j][2] * SCALE_LOG2E; if (c0 > r1 || p0) v = -1e30f; s[j][2] = v;
                v = s[j][3] * SCALE_LOG2E; if (c1 > r1 || p1) v = -1e30f; s[j][3] = v;
            }

            #pragma unroll
            for (int rr = 0; rr < 2; rr++) {
                float rm = -1e30f;
                #pragma unroll
                for (int j = 0; j < 8; j++)
                    rm = fmaxf(rm, fmaxf(s[j][2 * rr], s[j][2 * rr + 1]));
                rm = fmaxf(rm, __shfl_xor_sync(0xffffffffu, rm, 1));
                rm = fmaxf(rm, __shfl_xor_sync(0xffffffffu, rm, 2));
                const float mn    = fmaxf(m_i[rr], rm);
                const float alpha = exp2_fast(m_i[rr] - mn);
                m_i[rr] = mn;
                float rs = 0.f;
                #pragma unroll
                for (int j = 0; j < 8; j++) {
                    s[j][2 * rr    ] = exp2_fast(s[j][2 * rr    ] - mn);
                    s[j][2 * rr + 1] = exp2_fast(s[j][2 * rr + 1] - mn);
                    rs += s[j][2 * rr] + s[j][2 * rr + 1];
                }
                rs += __shfl_xor_sync(0xffffffffu, rs, 1);
                rs += __shfl_xor_sync(0xffffffffu, rs, 2);
                l_i[rr] = l_i[rr] * alpha + rs;
                #pragma unroll
                for (int j = 0; j < 8; j++) {
                    o[j][2 * rr    ] *= alpha;
                    o[j][2 * rr + 1] *= alpha;
                }
            }

            #pragma unroll
            for (int j = 0; j < 8; j++) {
                __nv_bfloat16 h0, l0, h1, l1, h2, l2, h3, l3;
                split_bf(s[j][0], h0, l0); split_bf(s[j][1], h1, l1);
                split_bf(s[j][2], h2, l2); split_bf(s[j][3], h3, l3);
                const int p0 = (rw + g) * QSTR + 8 * j + 2 * t;
                const int p1 = p0 + 8 * QSTR;
                *(unsigned*)&Ph[p0] = pk(h0, h1);
                *(unsigned*)&Pl[p0] = pk(l0, l1);
                *(unsigned*)&Ph[p1] = pk(h2, h3);
                *(unsigned*)&Pl[p1] = pk(l2, l3);
            }
            __syncwarp();

            // ---- O += P @ V: pair-blocked, term-major ----
            #pragma unroll
            for (int ks = 0; ks < 4; ks++) {
                const int kk = 16 * ks;
                unsigned ph[4], plr[4];
                ldsm4(ph,  Ph + rw * QSTR + kk + aoffQ);
                ldsm4(plr, Pl + rw * QSTR + kk + aoffQ);
                #pragma unroll
                for (int p = 0; p < 2; p++) {
                    unsigned bh0[4], bl0[4], bh1[4], bl1[4];
                    ldsm4(bh0, Vh + (32 * p     ) * QSTR + kk + boffQ);
                    ldsm4(bl0, Vl + (32 * p     ) * QSTR + kk + boffQ);
                    ldsm4(bh1, Vh + (32 * p + 16) * QSTR + kk + boffQ);
                    ldsm4(bl1, Vl + (32 * p + 16) * QSTR + kk + boffQ);
                    const int j0 = 4 * p;
                    mma16(o[j0 + 0], ph, bh0[0], bh0[1]);
                    mma16(o[j0 + 1], ph, bh0[2], bh0[3]);
                    mma16(o[j0 + 2], ph, bh1[0], bh1[1]);
                    mma16(o[j0 + 3], ph, bh1[2], bh1[3]);
                    mma16(o[j0 + 0], plr, bh0[0], bh0[1]);
                    mma16(o[j0 + 1], plr, bh0[2], bh0[3]);
                    mma16(o[j0 + 2], plr, bh1[0], bh1[1]);
                    mma16(o[j0 + 3], plr, bh1[2], bh1[3]);
                    mma16(o[j0 + 0], ph, bl0[0], bl0[1]);
                    mma16(o[j0 + 1], ph, bl0[2], bl0[3]);
                    mma16(o[j0 + 2], ph, bl1[0], bl1[1]);
                    mma16(o[j0 + 3], ph, bl1[2], bl1[3]);
                }
            }
        }
        __syncthreads();
    }

    const float inv0 = 1.f / l_i[0];
    const float inv1 = 1.f / l_i[1];
    const int row0 = qt * 128 + rw + g;
    const size_t d0 = ((size_t)b * SEQ + row0    ) * D_MODEL + h * D_HEAD;
    const size_t d1 = ((size_t)b * SEQ + row0 + 8) * D_MODEL + h * D_HEAD;
    #pragma unroll
    for (int j = 0; j < 8; j++) {
        const int cidx = 8 * j + 2 * t;
        __nv_bfloat16 h0, l0, h1, l1, h2, l2, h3, l3;
        split_bf(o[j][0] * inv0, h0, l0); split_bf(o[j][1] * inv0, h1, l1);
        split_bf(o[j][2] * inv1, h2, l2); split_bf(o[j][3] * inv1, h3, l3);
        *(unsigned*)&g_ch[d0 + cidx] = pk(h0, h1);
        *(unsigned*)&g_cl[d0 + cidx] = pk(l0, l1);
        *(unsigned*)&g_ch[d1 + cidx] = pk(h2, h3);
        *(unsigned*)&g_cl[d1 + cidx] = pk(l2, l3);
    }
}

// ---------------- launch ----------------------------------------------------
extern "C" void kernel_launch(void* const* d_in, const int* in_sizes, int n_in,
                              void* d_out, int out_size)
{
    (void)in_sizes; (void)n_in; (void)out_size;
    const float* x  = (const float*)d_in[0];
    const float* Qw = (const float*)d_in[1];
    const float* Kw = (const float*)d_in[2];
    const float* Vw = (const float*)d_in[3];
    const float* Ow = (const float*)d_in[4];
    const unsigned char* pm = (const unsigned char*)d_in[5];
    float* out = (float*)d_out;

    cudaFuncSetAttribute(attn_mma, cudaFuncAttributeMaxDynamicSharedMemorySize, ATTN_SMEM);
    cudaFuncSetAttribute(gemm_qkv, cudaFuncAttributeMaxDynamicSharedMemorySize, GEMM_SMEM);
    cudaFuncSetAttribute(gemm_out, cudaFuncAttributeMaxDynamicSharedMemorySize, GEMM_SMEM);

    split_all<<<12288, 256>>>(x, Qw, Kw, Vw, Ow);

    dim3 gq(D_MODEL / 128, MTOT / 128, 3);        // 8 x 64 x 3
    gemm_qkv<<<gq, 256, GEMM_SMEM>>>();

    dim3 ga(SEQ / 128, NUM_HEADS, BATCH);         // 16 x 16 x 4
    attn_mma<<<ga, 256, ATTN_SMEM>>>(pm);

    dim3 go(D_MODEL / 128, MTOT / 128);           // 8 x 64
    gemm_out<<<go, 256, GEMM_SMEM>>>(out);
}